// round 3
// baseline (speedup 1.0000x reference)
#include <cuda_runtime.h>

#define NN 50000
#define EE 800000
#define DD 128
#define BB 100
#define LSLOPE 0.01f
typedef unsigned long long u64;

#define FMA2(d,a,b,c) asm("fma.rn.f32x2 %0, %1, %2, %3;" : "=l"(d) : "l"(a), "l"(b), "l"(c))
#define PACK2(d,x)    asm("mov.b64 %0, {%1, %1};" : "=l"(d) : "r"(__float_as_uint(x)))
#define UNPK2(lo,hi,v) asm("mov.b64 {%0, %1}, %2;" : "=r"(lo), "=r"(hi) : "l"(v))

__device__ float d_aterm[NN*DD];
__device__ float d_bterm[NN*DD];
__device__ float d_c1[NN*DD];
__device__ float d_hfsum[NN*DD];
__device__ float d_npool[BB*DD];
__device__ float d_epool[BB*DD];
__device__ float d_gpool[BB*DD];
__device__ float d_gnew[BB*DD];
__device__ int   d_deg[NN];
__device__ int   d_nncnt[BB];
__device__ int   d_necnt[BB];

__device__ __forceinline__ float lrelu(float x){ return x > 0.f ? x : LSLOPE*x; }

__device__ __forceinline__ void red4(float* p, float4 v){
  asm volatile("red.global.add.v4.f32 [%0], {%1, %2, %3, %4};"
               :: "l"(p), "f"(v.x), "f"(v.y), "f"(v.z), "f"(v.w) : "memory");
}

__device__ __forceinline__ void unpack_acc(const u64* a, float* v){
  unsigned lo, hi;
  UNPK2(lo,hi,a[0]); v[0]=__uint_as_float(lo); v[1]=__uint_as_float(hi);
  UNPK2(lo,hi,a[1]); v[2]=__uint_as_float(lo); v[3]=__uint_as_float(hi);
  UNPK2(lo,hi,a[2]); v[4]=__uint_as_float(lo); v[5]=__uint_as_float(hi);
  UNPK2(lo,hi,a[3]); v[6]=__uint_as_float(lo); v[7]=__uint_as_float(hi);
}

// acc(4 rows x 8 cols as f32x2) += As(64x128 smem) @ W(128x128 gmem row-major)
__device__ __forceinline__ void mm_pass(const float* As, const float* __restrict__ W,
                                        u64 acc[4][4], float* Bs, int ty, int tx, int tid)
{
  #pragma unroll 1
  for (int k0 = 0; k0 < 128; k0 += 16) {
    __syncthreads();
    {
      int kr = tid >> 4, cc = (tid & 15) << 3;
      const float4* s4 = reinterpret_cast<const float4*>(W + (k0 + kr)*DD + cc);
      float4* t4 = reinterpret_cast<float4*>(Bs + kr*DD + cc);
      t4[0] = s4[0]; t4[1] = s4[1];
    }
    __syncthreads();
    #pragma unroll 4
    for (int k = 0; k < 16; ++k) {
      const float* br = Bs + k*DD;
      u64 b0 = *reinterpret_cast<const u64*>(br + tx*4);
      u64 b1 = *reinterpret_cast<const u64*>(br + tx*4 + 2);
      u64 b2 = *reinterpret_cast<const u64*>(br + 64 + tx*4);
      u64 b3 = *reinterpret_cast<const u64*>(br + 64 + tx*4 + 2);
      #pragma unroll
      for (int i = 0; i < 4; ++i) {
        u64 aa; PACK2(aa, As[(ty*4 + i)*DD + k0 + k]);
        FMA2(acc[i][0], aa, b0, acc[i][0]);
        FMA2(acc[i][1], aa, b1, acc[i][1]);
        FMA2(acc[i][2], aa, b2, acc[i][2]);
        FMA2(acc[i][3], aa, b3, acc[i][3]);
      }
    }
  }
}

#define ZACC(acc) { _Pragma("unroll") for (int zi=0; zi<4; ++zi){ _Pragma("unroll") for (int zj=0; zj<4; ++zj) acc[zi][zj]=0ull; } }

__global__ void kInit(){
  int idx = blockIdx.x*blockDim.x + threadIdx.x;
  if (idx < NN*DD) d_hfsum[idx] = 0.f;
  if (idx < BB*DD) { d_npool[idx]=0.f; d_epool[idx]=0.f; d_gpool[idx]=0.f; }
  if (idx < NN) d_deg[idx] = 0;
  if (idx < BB) { d_nncnt[idx]=0; d_necnt[idx]=0; }
}

__global__ void kCounts(const int* __restrict__ dst, const int* __restrict__ n2g){
  int idx = blockIdx.x*blockDim.x + threadIdx.x;
  if (idx < EE) atomicAdd(&d_deg[dst[idx]], 1);
  if (idx < NN) atomicAdd(&d_nncnt[n2g[idx]], 1);
}

// Per-node precompute: h, u, aterm, bterm, c1
__global__ __launch_bounds__(256) void kA(
    const float* __restrict__ node, const float* __restrict__ graph,
    const float* __restrict__ Wn, const float* __restrict__ bn,
    const float* __restrict__ Wg, const float* __restrict__ bg,
    const float* __restrict__ Weu, const float* __restrict__ beu,
    const float* __restrict__ Wnu, const float* __restrict__ bnu)
{
  extern __shared__ float sm[];
  float* Hs = sm; float* Us = sm + 64*DD; float* Bs = sm + 2*64*DD;
  int tid = threadIdx.x, tx = tid & 15, ty = tid >> 4;
  int row0 = blockIdx.x * 64, c0 = tx*4, cB = 64 + tx*4;

  for (int i = tid; i < 64*32; i += 256) {
    int n = row0 + (i >> 5), q = i & 31;
    float4 v = make_float4(0,0,0,0), g = v;
    if (n < NN) {
      v = reinterpret_cast<const float4*>(node)[(size_t)n*32 + q];
      g = reinterpret_cast<const float4*>(graph)[(size_t)n*32 + q];
    }
    reinterpret_cast<float4*>(Hs)[i] = v;
    reinterpret_cast<float4*>(Us)[i] = g;
  }

  u64 acc[4][4];
  ZACC(acc); mm_pass(Hs, Wn, acc, Bs, ty, tx, tid);
  __syncthreads();
  #pragma unroll
  for (int i=0;i<4;i++){
    float v[8]; unpack_acc(acc[i], v);
    float* hr = Hs + (ty*4+i)*DD;
    hr[c0]=lrelu(v[0]+bn[c0]); hr[c0+1]=lrelu(v[1]+bn[c0+1]);
    hr[c0+2]=lrelu(v[2]+bn[c0+2]); hr[c0+3]=lrelu(v[3]+bn[c0+3]);
    hr[cB]=lrelu(v[4]+bn[cB]); hr[cB+1]=lrelu(v[5]+bn[cB+1]);
    hr[cB+2]=lrelu(v[6]+bn[cB+2]); hr[cB+3]=lrelu(v[7]+bn[cB+3]);
  }
  ZACC(acc); mm_pass(Us, Wg, acc, Bs, ty, tx, tid);
  __syncthreads();
  #pragma unroll
  for (int i=0;i<4;i++){
    float v[8]; unpack_acc(acc[i], v);
    float* ur = Us + (ty*4+i)*DD;
    ur[c0]=lrelu(v[0]+bg[c0]); ur[c0+1]=lrelu(v[1]+bg[c0+1]);
    ur[c0+2]=lrelu(v[2]+bg[c0+2]); ur[c0+3]=lrelu(v[3]+bg[c0+3]);
    ur[cB]=lrelu(v[4]+bg[cB]); ur[cB+1]=lrelu(v[5]+bg[cB+1]);
    ur[cB+2]=lrelu(v[6]+bg[cB+2]); ur[cB+3]=lrelu(v[7]+bg[cB+3]);
  }

  ZACC(acc); mm_pass(Hs, Weu, acc, Bs, ty, tx, tid);       // aterm = h@Weu1
  #pragma unroll
  for (int i=0;i<4;i++){
    int n = row0 + ty*4 + i; if (n >= NN) continue;
    float v[8]; unpack_acc(acc[i], v);
    *reinterpret_cast<float4*>(d_aterm + (size_t)n*DD + c0) = make_float4(v[0],v[1],v[2],v[3]);
    *reinterpret_cast<float4*>(d_aterm + (size_t)n*DD + cB) = make_float4(v[4],v[5],v[6],v[7]);
  }

  ZACC(acc); mm_pass(Hs, Weu + 128*DD, acc, Bs, ty, tx, tid);  // bterm = h@Weu2 + u@Weu4 + beu
  mm_pass(Us, Weu + 384*DD, acc, Bs, ty, tx, tid);
  #pragma unroll
  for (int i=0;i<4;i++){
    int n = row0 + ty*4 + i; if (n >= NN) continue;
    float v[8]; unpack_acc(acc[i], v);
    *reinterpret_cast<float4*>(d_bterm + (size_t)n*DD + c0) =
      make_float4(v[0]+beu[c0], v[1]+beu[c0+1], v[2]+beu[c0+2], v[3]+beu[c0+3]);
    *reinterpret_cast<float4*>(d_bterm + (size_t)n*DD + cB) =
      make_float4(v[4]+beu[cB], v[5]+beu[cB+1], v[6]+beu[cB+2], v[7]+beu[cB+3]);
  }

  ZACC(acc); mm_pass(Hs, Wnu, acc, Bs, ty, tx, tid);           // c1 = h@Wnu1 + u@Wnu3 + bnu
  mm_pass(Us, Wnu + 256*DD, acc, Bs, ty, tx, tid);
  #pragma unroll
  for (int i=0;i<4;i++){
    int n = row0 + ty*4 + i; if (n >= NN) continue;
    float v[8]; unpack_acc(acc[i], v);
    *reinterpret_cast<float4*>(d_c1 + (size_t)n*DD + c0) =
      make_float4(v[0]+bnu[c0], v[1]+bnu[c0+1], v[2]+bnu[c0+2], v[3]+bnu[c0+3]);
    *reinterpret_cast<float4*>(d_c1 + (size_t)n*DD + cB) =
      make_float4(v[4]+bnu[cB], v[5]+bnu[cB+1], v[6]+bnu[cB+2], v[7]+bnu[cB+3]);
  }
}

// Edge kernel: f=lrelu(edge@We+be); f_new=lrelu(f@Weu3+aterm[src]+bterm[dst]);
// writes edge output (+residual); scatter-adds f_new to hfsum[dst].
__global__ __launch_bounds__(256) void kB(
    const float* __restrict__ edge, const int* __restrict__ src, const int* __restrict__ dst,
    const float* __restrict__ We, const float* __restrict__ be,
    const float* __restrict__ Weu, float* __restrict__ out_edge)
{
  extern __shared__ float sm[];
  float* Es = sm; float* Fs = sm + 64*DD; float* Bs = sm + 2*64*DD;
  int tid = threadIdx.x, tx = tid & 15, ty = tid >> 4;
  long row0 = (long)blockIdx.x * 64;
  int c0 = tx*4, cB = 64 + tx*4;

  for (int i = tid; i < 64*32; i += 256)
    reinterpret_cast<float4*>(Es)[i] = reinterpret_cast<const float4*>(edge)[row0*32 + i];

  u64 acc[4][4];
  ZACC(acc); mm_pass(Es, We, acc, Bs, ty, tx, tid);
  __syncthreads();
  #pragma unroll
  for (int i=0;i<4;i++){
    float v[8]; unpack_acc(acc[i], v);
    float* fr = Fs + (ty*4+i)*DD;
    fr[c0]=lrelu(v[0]+be[c0]); fr[c0+1]=lrelu(v[1]+be[c0+1]);
    fr[c0+2]=lrelu(v[2]+be[c0+2]); fr[c0+3]=lrelu(v[3]+be[c0+3]);
    fr[cB]=lrelu(v[4]+be[cB]); fr[cB+1]=lrelu(v[5]+be[cB+1]);
    fr[cB+2]=lrelu(v[6]+be[cB+2]); fr[cB+3]=lrelu(v[7]+be[cB+3]);
  }
  ZACC(acc); mm_pass(Fs, Weu + 256*DD, acc, Bs, ty, tx, tid);

  #pragma unroll
  for (int i=0;i<4;i++){
    int r = ty*4 + i; long e = row0 + r;
    int s = src[e], d = dst[e];
    float v[8]; unpack_acc(acc[i], v);
    const float4* at = reinterpret_cast<const float4*>(d_aterm + (size_t)s*DD);
    const float4* bt = reinterpret_cast<const float4*>(d_bterm + (size_t)d*DD);
    float4 a0 = at[tx], a1 = at[16+tx], b0 = bt[tx], b1 = bt[16+tx];
    float f0=lrelu(v[0]+a0.x+b0.x), f1=lrelu(v[1]+a0.y+b0.y);
    float f2=lrelu(v[2]+a0.z+b0.z), f3=lrelu(v[3]+a0.w+b0.w);
    float f4=lrelu(v[4]+a1.x+b1.x), f5=lrelu(v[5]+a1.y+b1.y);
    float f6=lrelu(v[6]+a1.z+b1.z), f7=lrelu(v[7]+a1.w+b1.w);
    float4 e0 = reinterpret_cast<float4*>(Es)[r*32 + tx];
    float4 e1 = reinterpret_cast<float4*>(Es)[r*32 + 16 + tx];
    *reinterpret_cast<float4*>(out_edge + (size_t)e*DD + c0) = make_float4(f0+e0.x,f1+e0.y,f2+e0.z,f3+e0.w);
    *reinterpret_cast<float4*>(out_edge + (size_t)e*DD + cB) = make_float4(f4+e1.x,f5+e1.y,f6+e1.z,f7+e1.w);
    red4(d_hfsum + (size_t)d*DD + c0, make_float4(f0,f1,f2,f3));
    red4(d_hfsum + (size_t)d*DD + cB, make_float4(f4,f5,f6,f7));
  }
}

// Node update + pooling accumulation
__global__ __launch_bounds__(256) void kC(
    const float* __restrict__ node, const float* __restrict__ graph,
    const int* __restrict__ n2g, const float* __restrict__ Wnu,
    float* __restrict__ out_node)
{
  extern __shared__ float sm[];
  float* Hf = sm; float* Bs = sm + 64*DD;
  int*   sG = reinterpret_cast<int*>(sm + 80*DD);
  float* sD = sm + 80*DD + 64;
  int tid = threadIdx.x, tx = tid & 15, ty = tid >> 4;
  int row0 = blockIdx.x * 64, c0 = tx*4, cB = 64 + tx*4;

  for (int i = tid; i < 64*32; i += 256) {
    int n = row0 + (i >> 5), q = i & 31;
    float4 v = make_float4(0,0,0,0);
    if (n < NN) v = reinterpret_cast<const float4*>(d_hfsum)[(size_t)n*32 + q];
    reinterpret_cast<float4*>(Hf)[i] = v;
  }
  if (tid < 64) {
    int n = row0 + tid, g = 0, dg = 0;
    if (n < NN) { g = n2g[n]; dg = d_deg[n]; atomicAdd(&d_necnt[g], dg); }
    sG[tid] = g;
    sD[tid] = 1.f / fmaxf((float)dg, 1.f);
  }
  __syncthreads();

  #pragma unroll
  for (int i=0;i<4;i++){
    int r = ty*4+i, n = row0 + r; if (n >= NN) continue;
    int g = sG[r];
    float4 h0 = reinterpret_cast<float4*>(Hf)[r*32 + tx];
    float4 h1 = reinterpret_cast<float4*>(Hf)[r*32 + 16 + tx];
    red4(d_epool + g*DD + c0, h0);
    red4(d_epool + g*DD + cB, h1);
    float4 g0 = reinterpret_cast<const float4*>(graph)[(size_t)n*32 + tx];
    float4 g1 = reinterpret_cast<const float4*>(graph)[(size_t)n*32 + 16 + tx];
    red4(d_gpool + g*DD + c0, g0);
    red4(d_gpool + g*DD + cB, g1);
    float rd = sD[r];
    h0.x*=rd; h0.y*=rd; h0.z*=rd; h0.w*=rd;
    h1.x*=rd; h1.y*=rd; h1.z*=rd; h1.w*=rd;
    reinterpret_cast<float4*>(Hf)[r*32 + tx] = h0;
    reinterpret_cast<float4*>(Hf)[r*32 + 16 + tx] = h1;
  }

  u64 acc[4][4];
  ZACC(acc); mm_pass(Hf, Wnu + 128*DD, acc, Bs, ty, tx, tid);  // hf@Wnu2

  #pragma unroll
  for (int i=0;i<4;i++){
    int r = ty*4+i, n = row0 + r; if (n >= NN) continue;
    float v[8]; unpack_acc(acc[i], v);
    const float* cr = d_c1 + (size_t)n*DD;
    float f0=lrelu(v[0]+cr[c0]),   f1=lrelu(v[1]+cr[c0+1]);
    float f2=lrelu(v[2]+cr[c0+2]), f3=lrelu(v[3]+cr[c0+3]);
    float f4=lrelu(v[4]+cr[cB]),   f5=lrelu(v[5]+cr[cB+1]);
    float f6=lrelu(v[6]+cr[cB+2]), f7=lrelu(v[7]+cr[cB+3]);
    float4 n0 = reinterpret_cast<const float4*>(node)[(size_t)n*32 + tx];
    float4 n1 = reinterpret_cast<const float4*>(node)[(size_t)n*32 + 16 + tx];
    *reinterpret_cast<float4*>(out_node + (size_t)n*DD + c0) = make_float4(f0+n0.x,f1+n0.y,f2+n0.z,f3+n0.w);
    *reinterpret_cast<float4*>(out_node + (size_t)n*DD + cB) = make_float4(f4+n1.x,f5+n1.y,f6+n1.z,f7+n1.w);
    int g = sG[r];
    red4(d_npool + g*DD + c0, make_float4(f0,f1,f2,f3));
    red4(d_npool + g*DD + cB, make_float4(f4,f5,f6,f7));
  }
}

// Graph update
__global__ void kD(const float* __restrict__ Wnu, const float* __restrict__ bnu){
  __shared__ float sp[3*DD];
  int g = blockIdx.x, j = threadIdx.x;
  float rn = 1.f / fmaxf((float)d_nncnt[g], 1.f);
  float re = 1.f / fmaxf((float)d_necnt[g], 1.f);
  sp[j]      = d_npool[g*DD+j]*rn;
  sp[DD+j]   = d_epool[g*DD+j]*re;
  sp[2*DD+j] = d_gpool[g*DD+j]*rn;
  __syncthreads();
  float a = bnu[j];
  #pragma unroll 4
  for (int k = 0; k < 3*DD; ++k) a = fmaf(sp[k], Wnu[k*DD+j], a);
  d_gnew[g*DD+j] = lrelu(a);
}

// Broadcast graph output + residual
__global__ void kE(const float* __restrict__ graph, const int* __restrict__ n2g,
                   float* __restrict__ out_graph){
  int t = blockIdx.x*blockDim.x + threadIdx.x;    // one float4 each
  if (t >= NN*32) return;
  int n = t >> 5, q = t & 31;
  int g = n2g[n];
  float4 gv = reinterpret_cast<const float4*>(d_gnew)[g*32 + q];
  float4 rv = reinterpret_cast<const float4*>(graph)[(size_t)n*32 + q];
  reinterpret_cast<float4*>(out_graph)[t] = make_float4(gv.x+rv.x, gv.y+rv.y, gv.z+rv.z, gv.w+rv.w);
}

extern "C" void kernel_launch(void* const* d_in, const int* in_sizes, int n_in,
                              void* d_out, int out_size) {
  const float* node  = (const float*)d_in[0];
  const float* edge  = (const float*)d_in[1];
  const float* graph = (const float*)d_in[2];
  const int*   src   = (const int*)d_in[3];
  const int*   dst   = (const int*)d_in[4];
  const int*   n2g   = (const int*)d_in[5];
  const float* Wn  = (const float*)d_in[6];
  const float* bn  = (const float*)d_in[7];
  const float* We  = (const float*)d_in[8];
  const float* be  = (const float*)d_in[9];
  const float* Wg  = (const float*)d_in[10];
  const float* bg  = (const float*)d_in[11];
  const float* Weu = (const float*)d_in[12];
  const float* beu = (const float*)d_in[13];
  const float* Wnu = (const float*)d_in[14];
  const float* bnu = (const float*)d_in[15];
  float* out_node  = (float*)d_out;
  float* out_edge  = out_node + (size_t)NN*DD;
  float* out_graph = out_edge + (size_t)EE*DD;

  const int SMAB = (2*64*DD + 16*DD) * 4;              // 73728 B
  const int SMC  = (80*DD) * 4 + 64*4 + 64*4;          // 41472 B
  cudaFuncSetAttribute(kA, cudaFuncAttributeMaxDynamicSharedMemorySize, SMAB);
  cudaFuncSetAttribute(kB, cudaFuncAttributeMaxDynamicSharedMemorySize, SMAB);
  cudaFuncSetAttribute(kC, cudaFuncAttributeMaxDynamicSharedMemorySize, SMC);

  kInit<<<(NN*DD + 255)/256, 256>>>();
  kCounts<<<(EE + 255)/256, 256>>>(dst, n2g);
  kA<<<(NN + 63)/64, 256, SMAB>>>(node, graph, Wn, bn, Wg, bg, Weu, beu, Wnu, bnu);
  kB<<<EE/64, 256, SMAB>>>(edge, src, dst, We, be, Weu, out_edge);
  kC<<<(NN + 63)/64, 256, SMC>>>(node, graph, n2g, Wnu, out_node);
  kD<<<BB, DD>>>(Wnu, bnu);
  kE<<<(NN*32 + 255)/256, 256>>>(graph, n2g, out_graph);
}